// round 16
// baseline (speedup 1.0000x reference)
#include <cuda_runtime.h>
#include <math.h>

#define IMG_H 128
#define IMG_W 2048
#define HW    (IMG_H * IMG_W)
#define PAD 3
#define S 7
#define K2 49
#define CENTER 24
#define HP (IMG_H + 2*PAD)   // 134
#define WP2 2064             // padded row stride (elements)
#define CUTOFF 2.0f
#define NBINS (IMG_H * IMG_W)  // 262144 = 1<<18
#define NCHUNK 256
#define MAXP  1048576
#define NPREP 1081             // ceil(HP*WP2/256)

// ---- device-global scratch (statically zero-initialized at load) ----
__device__ float         g_pr[HP * WP2];
__device__ unsigned char g_pa[HP * WP2];
__device__ int      g_roles[6];
__device__ unsigned g_hist[NBINS];     // zero invariant: re-zeroed by scan
__device__ unsigned g_cursor[NBINS];
__device__ unsigned g_bsum[NCHUNK];
__device__ unsigned g_bbase[NCHUNK];
__device__ unsigned g_ctr;
__device__ unsigned g_binslot[MAXP];   // bin(18b) | slot(14b)
__device__ uint4    g_pay[MAXP];       // {ur_bits, (y<<16)|x, orig_idx, 0}

// compile-time patch offsets: off[k] = (k/7)*WP2 + (k%7)
#define OROW(dy) (dy)*WP2+0,(dy)*WP2+1,(dy)*WP2+2,(dy)*WP2+3,(dy)*WP2+4,(dy)*WP2+5,(dy)*WP2+6
__constant__ int c_off[K2] = { OROW(0), OROW(1), OROW(2), OROW(3), OROW(4), OROW(5), OROW(6) };

struct WParams { float w[K2]; float A[K2]; };   // weights + exact thresholds
struct Roles { int ir, a64, iu, ipx, ipy, w64; };

// PTX shl.b32 clamps shift amounts >= 32 (incl. reinterpreted negatives) to
// produce 0 — avoids C++ UB and lets class 0 self-cancel (no guard needed).
__device__ __forceinline__ unsigned shl_clamp(unsigned x, int s) {
    unsigned r;
    asm("shl.b32 %0, %1, %2;" : "=r"(r) : "r"(x), "r"(s));
    return r;
}

// vote for class c (0..19); c==0 contributes nothing (both shifts clamp to 0).
// v_lo: classes 1..10 at bits 3c-3 (c=11 spills into bits 30+, harmless).
// v_hi: classes 11..19 at bits 3c-33.
__device__ __forceinline__ void vote_class(unsigned& v_lo, unsigned& v_hi, int c) {
    v_lo += shl_clamp(1u, 3 * c - 3);
    v_hi += shl_clamp(1u, 3 * c - 33);
}

// ------- role + dtype detection (trimmed: ~100 L2-hot loads) ---------------
__device__ Roles compute_roles(const unsigned* a0, const unsigned* a1,
                               const unsigned* b0, const unsigned* b1,
                               const unsigned* b2)
{
    Roles R;
    unsigned m0 = 0;
    for (int i = 0; i < 16; i++) m0 = max(m0, a0[i]);
    R.ir = (m0 > 0x10000u) ? 0 : 1;                 // float range image
    const unsigned* paw = (R.ir == 0) ? a1 : a0;
    unsigned oddA = 0;
    for (int i = 1; i < 32; i += 2) oddA = max(oddA, paw[i]);
    R.a64 = (oddA == 0);   // int64: odd 32-bit words all zero

    unsigned n0 = 0, n1 = 0;
    for (int i = 0; i < 16; i++) { n0 = max(n0, b0[i]); n1 = max(n1, b1[i]); }
    R.iu = (n0 > 0x10000u) ? 0 : (n1 > 0x10000u) ? 1 : 2;
    int r0 = (R.iu == 0) ? 1 : 0;
    int r1 = (R.iu == 2) ? 1 : 2;
    const unsigned* c0 = (r0 == 0) ? b0 : (r0 == 1) ? b1 : b2;
    const unsigned* c1 = (r1 == 0) ? b0 : (r1 == 1) ? b1 : b2;
    unsigned oddC = 0;
    for (int i = 1; i < 32; i += 2) oddC = max(oddC, c0[i]);
    R.w64 = (oddC == 0);

    unsigned v0 = 0, v1 = 0;
    if (R.w64) {
        for (int i = 0; i < 16; i++) { v0 = max(v0, c0[2 * i]); v1 = max(v1, c1[2 * i]); }
    } else {
        for (int i = 0; i < 16; i++) { v0 = max(v0, c0[i]); v1 = max(v1, c1[i]); }
    }
    R.ipx = (v0 >= 128u) ? r0 : r1;   // px >= 128 among 16 samples w.h.p.
    R.ipy = (R.ipx == r0) ? r1 : r0;
    return R;
}

// ---- fused: blocks [0,NPREP) build padded images; rest histogram ----------
__global__ void __launch_bounds__(256)
prephist_kernel(const void* __restrict__ A0,
                const void* __restrict__ A1,
                const void* __restrict__ B0,
                const void* __restrict__ B1,
                const void* __restrict__ B2, int P)
{
    __shared__ Roles Rs;
    if (threadIdx.x == 0) {
        Rs = compute_roles((const unsigned*)A0, (const unsigned*)A1,
                           (const unsigned*)B0, (const unsigned*)B1,
                           (const unsigned*)B2);
        if (blockIdx.x == 0) {
            g_roles[0] = Rs.ir;  g_roles[1] = Rs.a64;
            g_roles[2] = Rs.iu;  g_roles[3] = Rs.ipx;
            g_roles[4] = Rs.ipy; g_roles[5] = Rs.w64;
            g_ctr = 0u;
        }
    }
    __syncthreads();

    if (blockIdx.x < NPREP) {
        // ---- image prep section ----
        int idx = blockIdx.x * 256 + threadIdx.x;
        if (idx >= HP * WP2) return;
        const float* pr_in = (const float*)(Rs.ir == 0 ? A0 : A1);
        const void*  pa_in = (Rs.ir == 0 ? A1 : A0);
        int y = idx / WP2, x = idx - y * WP2;
        float v = 0.0f;
        int   c = 0;
        if (y >= PAD && y < IMG_H + PAD && x >= PAD && x < IMG_W + PAD) {
            int src = (y - PAD) * IMG_W + (x - PAD);
            v = pr_in[src];
            c = Rs.a64 ? (int)((const long long*)pa_in)[src]
                       : ((const int*)pa_in)[src];
        }
        if (v < 0.0f) v = __int_as_float(0x7f800000);  // invalid -> +inf
        g_pr[idx] = v;
        g_pa[idx] = (unsigned char)c;
    } else {
        // ---- histogram section (g_hist zero: static init / scan re-zero) ----
        int p = (blockIdx.x - NPREP) * 256 + threadIdx.x;
        if (p >= P) return;
        const void* pxv = (Rs.ipx == 0 ? B0 : Rs.ipx == 1 ? B1 : B2);
        const void* pyv = (Rs.ipy == 0 ? B0 : Rs.ipy == 1 ? B1 : B2);
        int x, y;
        if (Rs.w64) {
            x = (int)((const long long*)pxv)[p];
            y = (int)((const long long*)pyv)[p];
        } else {
            x = ((const int*)pxv)[p];
            y = ((const int*)pyv)[p];
        }
        unsigned bin = (unsigned)(y * IMG_W + x);
        unsigned slot = atomicAdd(&g_hist[bin], 1u);
        g_binslot[p] = bin | (slot << 18);     // slot < 16384 w.p. ~1
    }
}

// -------- scan: block-exclusive into cursor; re-zero hist for next replay --
__global__ void __launch_bounds__(1024) scan_kernel() {
    int i = blockIdx.x * 1024 + threadIdx.x;
    unsigned v = g_hist[i];
    g_hist[i] = 0u;                        // maintain zero invariant
    unsigned inc = v;
#pragma unroll
    for (int o = 1; o < 32; o <<= 1) {
        unsigned n = __shfl_up_sync(0xffffffffu, inc, o);
        if ((threadIdx.x & 31) >= o) inc += n;
    }
    __shared__ unsigned ws[32];
    if ((threadIdx.x & 31) == 31) ws[threadIdx.x >> 5] = inc;
    __syncthreads();
    if (threadIdx.x < 32) {
        unsigned wv = ws[threadIdx.x];
        unsigned wi = wv;
#pragma unroll
        for (int o = 1; o < 32; o <<= 1) {
            unsigned n = __shfl_up_sync(0xffffffffu, wi, o);
            if (threadIdx.x >= o) wi += n;
        }
        ws[threadIdx.x] = wi - wv;
        if (threadIdx.x == 31) g_bsum[blockIdx.x] = wi;
    }
    __syncthreads();
    g_cursor[i] = (inc - v) + ws[threadIdx.x >> 5];  // block-exclusive

    // decoupled chunk scan: last-arriving block scans g_bsum -> g_bbase
    __threadfence();
    __shared__ int lastf;
    if (threadIdx.x == 0) lastf = (atomicAdd(&g_ctr, 1u) == NCHUNK - 1);
    __syncthreads();
    if (lastf && threadIdx.x < NCHUNK) {
        unsigned bv = g_bsum[threadIdx.x];
        unsigned binc = bv;
#pragma unroll
        for (int o = 1; o < 32; o <<= 1) {
            unsigned n = __shfl_up_sync(0xffffffffu, binc, o);
            if ((threadIdx.x & 31) >= o) binc += n;
        }
        __shared__ unsigned ws2[8];
        if ((threadIdx.x & 31) == 31) ws2[threadIdx.x >> 5] = binc;
        __syncwarp();
        asm volatile("bar.sync 1, 256;" ::: "memory");
        unsigned wo = 0;
        for (int j = 0; j < (threadIdx.x >> 5); j++) wo += ws2[j];
        g_bbase[threadIdx.x] = (binc - bv) + wo;
    }
}

// ------- scatter (NO atomics): pos = cursor[bin] + cached slot -------------
__global__ void scatter_kernel(const void* __restrict__ B0,
                               const void* __restrict__ B1,
                               const void* __restrict__ B2, int P)
{
    int p = blockIdx.x * blockDim.x + threadIdx.x;
    if (p >= P) return;
    int iu = g_roles[2];
    const float* unproj = (const float*)(iu == 0 ? B0 : iu == 1 ? B1 : B2);
    unsigned bs   = g_binslot[p];            // coalesced
    unsigned bin  = bs & (NBINS - 1);
    unsigned slot = bs >> 18;
    unsigned x = bin & (IMG_W - 1);
    unsigned y = bin >> 11;
    unsigned pos = __ldg(&g_cursor[bin]) + __ldg(&g_bbase[bin >> 10]) + slot;
    g_pay[pos] = make_uint4(__float_as_uint(__ldg(&unproj[p])),
                            (y << 16) | x, (unsigned)p, 0u);
}

// ---- per-point label: mask precomputed; vote + argmax ---------------------
__device__ __forceinline__ int label_from_mask(
    unsigned m_lo, unsigned m_hi, float ur, const float* pr,
    const unsigned char* pa, const WParams& wp)
{
    unsigned v_lo = 0u, v_hi = 0u;

    if (__popc(m_lo) + __popc(m_hi) <= 6) {
        // FAST PATH: <=7 candidates incl. center -> all provably in the stable
        // top-7; remaining top-7 members exceed cutoff -> discarded class slot.
        unsigned long long m = (unsigned long long)m_lo
                             | ((unsigned long long)m_hi << 32)
                             | (1ull << CENTER);
        while (m) {
            int k = __ffsll((long long)m) - 1;
            m &= m - 1;
            int c = (int)__ldg(&pa[c_off[k]]);
            vote_class(v_lo, v_hi, c);        // c==0 self-cancels
        }
    } else {
        // SLOW PATH: C>=8 candidates -> stable top-7 are the 7 smallest
        // candidates. Key = (f32bits(d) << 6) | k (monotone, lowest-k ties ==
        // jax.lax.top_k stable order). d computed exactly as reference.
        unsigned long long cand = (unsigned long long)m_lo
                                | ((unsigned long long)m_hi << 32)
                                | (1ull << CENTER);
        unsigned long long t0 = ~0ull, t1 = ~0ull, t2 = ~0ull, t3 = ~0ull,
                           t4 = ~0ull, t5 = ~0ull, t6 = ~0ull;
        while (cand) {
            int k = __ffsll((long long)cand) - 1;
            cand &= cand - 1;
            float v = (k == CENTER) ? ur : __ldg(&pr[c_off[k]]);
            float d = fabsf(v - ur) * wp.w[k];
            unsigned long long key =
                ((unsigned long long)__float_as_uint(d) << 6) | (unsigned)k;
            if (key < t6) {
                t6 = key;
                if (t6 < t5) { unsigned long long s = t5; t5 = t6; t6 = s; }
                if (t5 < t4) { unsigned long long s = t4; t4 = t5; t5 = s; }
                if (t4 < t3) { unsigned long long s = t3; t3 = t4; t4 = s; }
                if (t3 < t2) { unsigned long long s = t2; t2 = t3; t3 = s; }
                if (t2 < t1) { unsigned long long s = t1; t1 = t2; t2 = s; }
                if (t1 < t0) { unsigned long long s = t0; t0 = t1; t1 = s; }
            }
        }
        unsigned long long ts[7] = {t0, t1, t2, t3, t4, t5, t6};
#pragma unroll
        for (int j = 0; j < 7; j++) {
            int k = (int)(ts[j] & 63ull);
            int c = (int)__ldg(&pa[c_off[k]]);
            vote_class(v_lo, v_hi, c);
        }
    }

    // argmax classes 1..19 via IMAX on key = n*32 + (32-c); all-zero -> 31 ->
    // class 1 — matches argmax(votes[:,1:-1])+1 exactly (lowest class ties).
    int best = 31;
#pragma unroll
    for (int c = 1; c <= 10; c++) {
        int n = (int)((v_lo >> (3 * c - 3)) & 7u);
        best = max(best, n * 32 + (32 - c));
    }
#pragma unroll
    for (int c = 11; c <= 19; c++) {
        int n = (int)((v_hi >> (3 * c - 33)) & 7u);
        best = max(best, n * 32 + (32 - c));
    }
    return 32 - (best & 31);
}

// ---------------- main KNN kernel: TWO sorted-adjacent points per thread ---
__global__ void __launch_bounds__(256)
knn_kernel(void* __restrict__ outv, int P, WParams wp)
{
    int i0 = (blockIdx.x * 256 + threadIdx.x) * 2;
    if (i0 >= P) return;
    bool has1 = (i0 + 1 < P);

    uint4 pay0 = g_pay[i0];
    uint4 pay1 = has1 ? g_pay[i0 + 1] : pay0;

    float ur0 = __uint_as_float(pay0.x);
    float ur1 = __uint_as_float(pay1.x);
    int base0 = (int)(pay0.y >> 16) * WP2 + (int)(pay0.y & 0xffffu);
    int base1 = (int)(pay1.y >> 16) * WP2 + (int)(pay1.y & 0xffffu);
    const float* pr0 = g_pr + base0;
    const float* pr1 = g_pr + base1;

    // Two independent branch-free mask passes back-to-back: ptxas interleaves
    // the chains, hiding LDG/FADD latency (issue slots currently ~37% idle).
    unsigned m_lo0 = 0u, m_hi0 = 0u, m_lo1 = 0u, m_hi1 = 0u;
#pragma unroll
    for (int k = 0; k < 32; k++) {
        if (k == CENTER) continue;
        float t = __ldg(&pr0[(k / S) * WP2 + (k % S)]) - ur0;
        if (fabsf(t) <= wp.A[k]) m_lo0 |= (1u << k);
    }
#pragma unroll
    for (int k = 32; k < K2; k++) {
        float t = __ldg(&pr0[(k / S) * WP2 + (k % S)]) - ur0;
        if (fabsf(t) <= wp.A[k]) m_hi0 |= (1u << (k - 32));
    }
#pragma unroll
    for (int k = 0; k < 32; k++) {
        if (k == CENTER) continue;
        float t = __ldg(&pr1[(k / S) * WP2 + (k % S)]) - ur1;
        if (fabsf(t) <= wp.A[k]) m_lo1 |= (1u << k);
    }
#pragma unroll
    for (int k = 32; k < K2; k++) {
        float t = __ldg(&pr1[(k / S) * WP2 + (k % S)]) - ur1;
        if (fabsf(t) <= wp.A[k]) m_hi1 |= (1u << (k - 32));
    }

    int w64 = g_roles[5];
    int lab0 = label_from_mask(m_lo0, m_hi0, ur0, pr0, g_pa + base0, wp);
    if (w64) ((long long*)outv)[pay0.z] = (long long)lab0;
    else     ((float*)outv)[pay0.z]     = (float)lab0;

    if (has1) {
        int lab1 = label_from_mask(m_lo1, m_hi1, ur1, pr1, g_pa + base1, wp);
        if (w64) ((long long*)outv)[pay1.z] = (long long)lab1;
        else     ((float*)outv)[pay1.z]     = (float)lab1;
    }
}

extern "C" void kernel_launch(void* const* d_in, const int* in_sizes, int n_in,
                              void* d_out, int out_size) {
    int hw_idx[2], p_idx[3], nh = 0, np_ = 0;
    for (int i = 0; i < n_in; i++) {
        if (in_sizes[i] == HW) { if (nh < 2) hw_idx[nh++] = i; }
        else                   { if (np_ < 3) p_idx[np_++] = i; }
    }
    const void* A0 = d_in[hw_idx[0]];
    const void* A1 = d_in[hw_idx[1]];
    const void* B0 = d_in[p_idx[0]];
    const void* B1 = d_in[p_idx[1]];
    const void* B2 = d_in[p_idx[2]];
    int P = out_size;

    WParams wp;
    {
        const double PI = 3.14159265358979323846;
        double g[K2], sum = 0.0;
        double mean = (S - 1) / 2.0;
        for (int yy = 0; yy < S; yy++)
            for (int xx = 0; xx < S; xx++) {
                double dx = xx - mean, dy = yy - mean;
                double e = exp(-(dx * dx + dy * dy) / 2.0) / (2.0 * PI);
                g[yy * S + xx] = e;
                sum += e;
            }
        for (int k = 0; k < K2; k++) wp.w[k] = (float)(1.0 - g[k] / sum);

        // Exact thresholds: A_k = max{ float a >= 0 : RN(a * w_k) <= 2.0f }.
        for (int k = 0; k < K2; k++) {
            volatile float w = wp.w[k];
            unsigned lo = 0u, hi = 0x7F7FFFFFu;     // [0, FLT_MAX]
            while (lo < hi) {
                unsigned mid = lo + (hi - lo + 1u) / 2u;
                float a; memcpy(&a, &mid, 4);
                volatile float d = a * w;
                if (d <= CUTOFF) lo = mid; else hi = mid - 1u;
            }
            float A; memcpy(&A, &lo, 4);
            wp.A[k] = A;
        }
    }

    int histblk = (P + 255) / 256;
    prephist_kernel<<<NPREP + histblk, 256>>>(A0, A1, B0, B1, B2, P);
    scan_kernel<<<NCHUNK, 1024>>>();
    scatter_kernel<<<(P + 255) / 256, 256>>>(B0, B1, B2, P);
    int pairs = (P + 1) / 2;
    knn_kernel<<<(pairs + 255) / 256, 256>>>(d_out, P, wp);
}

// round 17
// speedup vs baseline: 1.1130x; 1.1130x over previous
#include <cuda_runtime.h>
#include <math.h>

#define IMG_H 128
#define IMG_W 2048
#define HW    (IMG_H * IMG_W)
#define PAD 3
#define S 7
#define K2 49
#define CENTER 24
#define HP (IMG_H + 2*PAD)   // 134
#define WP2 2064             // padded row stride (elements)
#define CUTOFF 2.0f
#define NBINS (IMG_H * IMG_W)  // 262144 = 1<<18
#define NCHUNK 256
#define MAXP  1048576
#define NPREP 1081             // ceil(HP*WP2/256)

// ---- device-global scratch (statically zero-initialized at load) ----
__device__ float         g_pr[HP * WP2];
__device__ unsigned char g_pa[HP * WP2];
__device__ int      g_roles[6];
__device__ unsigned g_hist[NBINS];     // zero invariant: re-zeroed by scan
__device__ unsigned g_cursor[NBINS];
__device__ unsigned g_bsum[NCHUNK];
__device__ unsigned g_bbase[NCHUNK];
__device__ unsigned g_ctr;
__device__ unsigned g_binslot[MAXP];   // bin(18b) | slot(14b)
__device__ uint4    g_pay[MAXP];       // {ur_bits, (y<<16)|x, orig_idx, 0}

// compile-time patch offsets: off[k] = (k/7)*WP2 + (k%7)
#define OROW(dy) (dy)*WP2+0,(dy)*WP2+1,(dy)*WP2+2,(dy)*WP2+3,(dy)*WP2+4,(dy)*WP2+5,(dy)*WP2+6
__constant__ int c_off[K2] = { OROW(0), OROW(1), OROW(2), OROW(3), OROW(4), OROW(5), OROW(6) };

struct WParams { float w[K2]; float A[K2]; };   // weights + exact thresholds
struct Roles { int ir, a64, iu, ipx, ipy, w64; };

// ------- role + dtype detection: WARP-PARALLEL (lanes 0..31) ---------------
// 32 coalesced samples per test; failure prob <= 20^-32 / 16^-32.
__device__ Roles warp_roles(const unsigned* a0, const unsigned* a1,
                            const unsigned* b0, const unsigned* b1,
                            const unsigned* b2)
{
    int lane = threadIdx.x;   // caller guarantees threadIdx.x < 32
    Roles R;

    unsigned m0 = __reduce_max_sync(0xffffffffu, (lane < 16) ? a0[lane] : 0u);
    R.ir = (m0 > 0x10000u) ? 0 : 1;                 // float range image
    const unsigned* paw = (R.ir == 0) ? a1 : a0;
    unsigned oddA = __reduce_max_sync(0xffffffffu, paw[2 * lane + 1]);
    R.a64 = (oddA == 0);                            // int64: odd words all zero

    unsigned n0 = __reduce_max_sync(0xffffffffu, (lane < 16) ? b0[lane] : 0u);
    unsigned n1 = __reduce_max_sync(0xffffffffu, (lane < 16) ? b1[lane] : 0u);
    R.iu = (n0 > 0x10000u) ? 0 : (n1 > 0x10000u) ? 1 : 2;
    int r0 = (R.iu == 0) ? 1 : 0;
    int r1 = (R.iu == 2) ? 1 : 2;
    const unsigned* c0 = (r0 == 0) ? b0 : (r0 == 1) ? b1 : b2;
    const unsigned* c1 = (r1 == 0) ? b0 : (r1 == 1) ? b1 : b2;
    unsigned oddC = __reduce_max_sync(0xffffffffu, c0[2 * lane + 1]);
    R.w64 = (oddC == 0);

    unsigned v0, v1;
    if (R.w64) { v0 = c0[2 * lane]; v1 = c1[2 * lane]; }
    else       { v0 = c0[lane];     v1 = c1[lane];     }
    v0 = __reduce_max_sync(0xffffffffu, v0);
    v1 = __reduce_max_sync(0xffffffffu, v1);
    R.ipx = (v0 >= 128u) ? r0 : r1;   // px >= 128 among 32 samples w.h.p.
    R.ipy = (R.ipx == r0) ? r1 : r0;
    return R;
}

// ---- fused: blocks [0,NPREP) build padded images; rest histogram ----------
__global__ void __launch_bounds__(256)
prephist_kernel(const void* __restrict__ A0,
                const void* __restrict__ A1,
                const void* __restrict__ B0,
                const void* __restrict__ B1,
                const void* __restrict__ B2, int P)
{
    __shared__ Roles Rs;
    if (threadIdx.x < 32) {
        Roles r = warp_roles((const unsigned*)A0, (const unsigned*)A1,
                             (const unsigned*)B0, (const unsigned*)B1,
                             (const unsigned*)B2);
        if (threadIdx.x == 0) {
            Rs = r;
            if (blockIdx.x == 0) {
                g_roles[0] = r.ir;  g_roles[1] = r.a64;
                g_roles[2] = r.iu;  g_roles[3] = r.ipx;
                g_roles[4] = r.ipy; g_roles[5] = r.w64;
                g_ctr = 0u;
            }
        }
    }
    __syncthreads();

    if (blockIdx.x < NPREP) {
        // ---- image prep section ----
        int idx = blockIdx.x * 256 + threadIdx.x;
        if (idx >= HP * WP2) return;
        const float* pr_in = (const float*)(Rs.ir == 0 ? A0 : A1);
        const void*  pa_in = (Rs.ir == 0 ? A1 : A0);
        int y = idx / WP2, x = idx - y * WP2;
        float v = 0.0f;
        int   c = 0;
        if (y >= PAD && y < IMG_H + PAD && x >= PAD && x < IMG_W + PAD) {
            int src = (y - PAD) * IMG_W + (x - PAD);
            v = pr_in[src];
            c = Rs.a64 ? (int)((const long long*)pa_in)[src]
                       : ((const int*)pa_in)[src];
        }
        if (v < 0.0f) v = __int_as_float(0x7f800000);  // invalid -> +inf
        g_pr[idx] = v;
        g_pa[idx] = (unsigned char)c;
    } else {
        // ---- histogram section (g_hist zero: static init / scan re-zero) ----
        int p = (blockIdx.x - NPREP) * 256 + threadIdx.x;
        if (p >= P) return;
        const void* pxv = (Rs.ipx == 0 ? B0 : Rs.ipx == 1 ? B1 : B2);
        const void* pyv = (Rs.ipy == 0 ? B0 : Rs.ipy == 1 ? B1 : B2);
        int x, y;
        if (Rs.w64) {
            x = (int)((const long long*)pxv)[p];
            y = (int)((const long long*)pyv)[p];
        } else {
            x = ((const int*)pxv)[p];
            y = ((const int*)pyv)[p];
        }
        unsigned bin = (unsigned)(y * IMG_W + x);
        unsigned slot = atomicAdd(&g_hist[bin], 1u);
        g_binslot[p] = bin | (slot << 18);     // slot < 16384 w.p. ~1
    }
}

// -------- scan: block-exclusive into cursor; re-zero hist for next replay --
__global__ void __launch_bounds__(1024) scan_kernel() {
    int i = blockIdx.x * 1024 + threadIdx.x;
    unsigned v = g_hist[i];
    g_hist[i] = 0u;                        // maintain zero invariant
    unsigned inc = v;
#pragma unroll
    for (int o = 1; o < 32; o <<= 1) {
        unsigned n = __shfl_up_sync(0xffffffffu, inc, o);
        if ((threadIdx.x & 31) >= o) inc += n;
    }
    __shared__ unsigned ws[32];
    if ((threadIdx.x & 31) == 31) ws[threadIdx.x >> 5] = inc;
    __syncthreads();
    if (threadIdx.x < 32) {
        unsigned wv = ws[threadIdx.x];
        unsigned wi = wv;
#pragma unroll
        for (int o = 1; o < 32; o <<= 1) {
            unsigned n = __shfl_up_sync(0xffffffffu, wi, o);
            if (threadIdx.x >= o) wi += n;
        }
        ws[threadIdx.x] = wi - wv;
        if (threadIdx.x == 31) g_bsum[blockIdx.x] = wi;
    }
    __syncthreads();
    g_cursor[i] = (inc - v) + ws[threadIdx.x >> 5];  // block-exclusive

    // decoupled chunk scan: last-arriving block scans g_bsum -> g_bbase
    __threadfence();
    __shared__ int lastf;
    if (threadIdx.x == 0) lastf = (atomicAdd(&g_ctr, 1u) == NCHUNK - 1);
    __syncthreads();
    if (lastf && threadIdx.x < NCHUNK) {
        unsigned bv = g_bsum[threadIdx.x];
        unsigned binc = bv;
#pragma unroll
        for (int o = 1; o < 32; o <<= 1) {
            unsigned n = __shfl_up_sync(0xffffffffu, binc, o);
            if ((threadIdx.x & 31) >= o) binc += n;
        }
        __shared__ unsigned ws2[8];
        if ((threadIdx.x & 31) == 31) ws2[threadIdx.x >> 5] = binc;
        __syncwarp();
        asm volatile("bar.sync 1, 256;" ::: "memory");
        unsigned wo = 0;
        for (int j = 0; j < (threadIdx.x >> 5); j++) wo += ws2[j];
        g_bbase[threadIdx.x] = (binc - bv) + wo;
    }
}

// ------- scatter (NO atomics): pos = cursor[bin] + cached slot -------------
__global__ void scatter_kernel(const void* __restrict__ B0,
                               const void* __restrict__ B1,
                               const void* __restrict__ B2, int P)
{
    int p = blockIdx.x * blockDim.x + threadIdx.x;
    if (p >= P) return;
    int iu = g_roles[2];
    const float* unproj = (const float*)(iu == 0 ? B0 : iu == 1 ? B1 : B2);
    unsigned bs   = g_binslot[p];            // coalesced
    unsigned bin  = bs & (NBINS - 1);
    unsigned slot = bs >> 18;
    unsigned x = bin & (IMG_W - 1);
    unsigned y = bin >> 11;
    unsigned pos = __ldg(&g_cursor[bin]) + __ldg(&g_bbase[bin >> 10]) + slot;
    g_pay[pos] = make_uint4(__float_as_uint(__ldg(&unproj[p])),
                            (y << 16) | x, (unsigned)p, 0u);
}

// ---------------- main KNN kernel (pixel-sorted order) ---------------------
__global__ void __launch_bounds__(128)
knn_kernel(void* __restrict__ outv, int P, WParams wp)
{
    int i = blockIdx.x * 128 + threadIdx.x;
    if (i >= P) return;

    uint4 pay = g_pay[i];
    float ur = __uint_as_float(pay.x);
    int x = (int)(pay.y & 0xffffu);
    int y = (int)(pay.y >> 16);

    int base = y * WP2 + x;          // patch top-left in padded coords
    const float*         pr = g_pr + base;
    const unsigned char* pa = g_pa + base;

    // Fast predicate pass with EXACT precomputed thresholds:
    //   RN(|v-ur| * w_k) <= 2.0f  <=>  |v-ur| <= A_k
    unsigned m_lo = 0u, m_hi = 0u;
#pragma unroll
    for (int k = 0; k < 32; k++) {
        if (k == CENTER) continue;
        float t = __ldg(&pr[(k / S) * WP2 + (k % S)]) - ur;
        if (fabsf(t) <= wp.A[k]) m_lo |= (1u << k);
    }
#pragma unroll
    for (int k = 32; k < K2; k++) {
        float t = __ldg(&pr[(k / S) * WP2 + (k % S)]) - ur;
        if (fabsf(t) <= wp.A[k]) m_hi |= (1u << (k - 32));
    }

    unsigned long long votes = 0ull;

    if (__popc(m_lo) + __popc(m_hi) <= 6) {
        // FAST PATH: <=7 candidates incl. center -> all provably in the stable
        // top-7; remaining top-7 members exceed cutoff -> discarded class slot.
        int cc = (int)__ldg(&pa[PAD * WP2 + PAD]);
        if (cc > 0) votes += 1ull << (3 * cc - 3);
        unsigned m = m_lo;
        while (m) {
            int k = __ffs(m) - 1;
            m &= m - 1;
            int c = (int)__ldg(&pa[c_off[k]]);
            if (c > 0) votes += 1ull << (3 * c - 3);
        }
        m = m_hi;
        while (m) {
            int k = __ffs(m) - 1;
            m &= m - 1;
            int c = (int)__ldg(&pa[c_off[k + 32]]);
            if (c > 0) votes += 1ull << (3 * c - 3);
        }
    } else {
        // SLOW PATH: C>=8 candidates -> stable top-7 are the 7 smallest
        // candidates. Key = (f32bits(d) << 6) | k (monotone, lowest-k ties ==
        // jax.lax.top_k stable order). d computed exactly as reference.
        unsigned long long cand = (unsigned long long)m_lo
                                | ((unsigned long long)m_hi << 32)
                                | (1ull << CENTER);
        unsigned long long t0 = ~0ull, t1 = ~0ull, t2 = ~0ull, t3 = ~0ull,
                           t4 = ~0ull, t5 = ~0ull, t6 = ~0ull;
        while (cand) {
            int k = __ffsll((long long)cand) - 1;
            cand &= cand - 1;
            float v = (k == CENTER) ? ur : __ldg(&pr[c_off[k]]);
            float d = fabsf(v - ur) * wp.w[k];
            unsigned long long key =
                ((unsigned long long)__float_as_uint(d) << 6) | (unsigned)k;
            if (key < t6) {
                t6 = key;
                if (t6 < t5) { unsigned long long s = t5; t5 = t6; t6 = s; }
                if (t5 < t4) { unsigned long long s = t4; t4 = t5; t5 = s; }
                if (t4 < t3) { unsigned long long s = t3; t3 = t4; t4 = s; }
                if (t3 < t2) { unsigned long long s = t2; t2 = t3; t3 = s; }
                if (t2 < t1) { unsigned long long s = t1; t1 = t2; t2 = s; }
                if (t1 < t0) { unsigned long long s = t0; t0 = t1; t1 = s; }
            }
        }
        unsigned long long ts[7] = {t0, t1, t2, t3, t4, t5, t6};
#pragma unroll
        for (int j = 0; j < 7; j++) {
            int k = (int)(ts[j] & 63ull);
            int c = (int)__ldg(&pa[c_off[k]]);
            if (c > 0) votes += 1ull << (3 * c - 3);
        }
    }

    // argmax classes 1..19 via IMAX on key = count*32 + (32-c):
    // count dominates; higher (32-c) == lower class wins ties; all-zero ->
    // key 31 (class 1) — matches argmax(votes[:,1:-1])+1 exactly.
    int best = 31;
    unsigned long long vv = votes;
#pragma unroll
    for (int c = 1; c <= 19; c++) {
        int key = ((int)vv & 7) * 32 + (32 - c);
        best = max(best, key);
        vv >>= 3;
    }
    int best_c = 32 - (best & 31);

    unsigned op = pay.z;
    if (g_roles[5]) ((long long*)outv)[op] = (long long)best_c;
    else            ((float*)outv)[op]     = (float)best_c;
}

extern "C" void kernel_launch(void* const* d_in, const int* in_sizes, int n_in,
                              void* d_out, int out_size) {
    int hw_idx[2], p_idx[3], nh = 0, np_ = 0;
    for (int i = 0; i < n_in; i++) {
        if (in_sizes[i] == HW) { if (nh < 2) hw_idx[nh++] = i; }
        else                   { if (np_ < 3) p_idx[np_++] = i; }
    }
    const void* A0 = d_in[hw_idx[0]];
    const void* A1 = d_in[hw_idx[1]];
    const void* B0 = d_in[p_idx[0]];
    const void* B1 = d_in[p_idx[1]];
    const void* B2 = d_in[p_idx[2]];
    int P = out_size;

    WParams wp;
    {
        const double PI = 3.14159265358979323846;
        double g[K2], sum = 0.0;
        double mean = (S - 1) / 2.0;
        for (int yy = 0; yy < S; yy++)
            for (int xx = 0; xx < S; xx++) {
                double dx = xx - mean, dy = yy - mean;
                double e = exp(-(dx * dx + dy * dy) / 2.0) / (2.0 * PI);
                g[yy * S + xx] = e;
                sum += e;
            }
        for (int k = 0; k < K2; k++) wp.w[k] = (float)(1.0 - g[k] / sum);

        // Exact thresholds: A_k = max{ float a >= 0 : RN(a * w_k) <= 2.0f }.
        for (int k = 0; k < K2; k++) {
            volatile float w = wp.w[k];
            unsigned lo = 0u, hi = 0x7F7FFFFFu;     // [0, FLT_MAX]
            while (lo < hi) {
                unsigned mid = lo + (hi - lo + 1u) / 2u;
                float a; memcpy(&a, &mid, 4);
                volatile float d = a * w;
                if (d <= CUTOFF) lo = mid; else hi = mid - 1u;
            }
            float A; memcpy(&A, &lo, 4);
            wp.A[k] = A;
        }
    }

    int histblk = (P + 255) / 256;
    prephist_kernel<<<NPREP + histblk, 256>>>(A0, A1, B0, B1, B2, P);
    scan_kernel<<<NCHUNK, 1024>>>();
    scatter_kernel<<<(P + 255) / 256, 256>>>(B0, B1, B2, P);
    knn_kernel<<<(P + 127) / 128, 128>>>(d_out, P, wp);
}